// round 10
// baseline (speedup 1.0000x reference)
#include <cuda_runtime.h>
#include <math.h>

#define ND 4096
#define BM 64
#define BN 64
#define BK 16
#define KSPLIT 2048   // splitK=2 boundary: two ascending sub-chains + one f32 add

// Scratch (allocation-free): low/high digit planes, 64 MB each.
static __device__ float g_low[(long long)ND * ND];
static __device__ float g_high[(long long)ND * ND];

// Elementwise digit split, replicating jnp semantics exactly.
__global__ void __launch_bounds__(256) prep_kernel(const float* __restrict__ x,
                                                   const float* __restrict__ r) {
    long long i = (long long)blockIdx.x * 256 + threadIdx.x;
    float xv = x[i];
    float rv = r[i];
    float xb = __fadd_rn(xv, rv);
    float low = fmodf(xb, 2291.0f);
    if (low < 0.0f) low = __fadd_rn(low, 2291.0f);   // jnp.mod sign fix (Q > 0)
    float high = rintf(__fdiv_rn(__fsub_rn(xb, low), 2291.0f));
    g_low[i] = low;
    g_high[i] = high;
}

// Fused triple-SGEMM replicating cublas splitK=2 rounding:
// per output element: chain0 = fp32 FMA chain over k=0..2047 ascending,
// chain1 over k=2048..4095 ascending, result = f32(chain0 + chain1).
// Epilogue replicates the reference combine exactly:
//   oL  = fp32(accL + b[j]);  v = f64(oL) + 2291.0*f64(accH)  (no DFMA)
//   out = fp32( (fp32(v) - accR) * 2^-8 )
__global__ void __launch_bounds__(256) gemm3_split2_kernel(
        const float* __restrict__ Ar,      // r
        const float* __restrict__ W,
        const float* __restrict__ bvec,
        float* __restrict__ out) {
    __shared__ float As[3][BK][BM];   // [r, low, high], transposed [k][m]
    __shared__ float Bs[BK][BN];

    const int tid  = threadIdx.x;
    const int tx   = tid & 15;        // output col group
    const int ty   = tid >> 4;        // output row group
    const int row0 = blockIdx.y * BM;
    const int col0 = blockIdx.x * BN;

    const int lrow = tid >> 2;          // 0..63
    const int lk   = (tid & 3) << 2;    // 0,4,8,12
    const int brow = tid >> 4;          // 0..15
    const int bcol = (tid & 15) << 2;   // 0..60

    // Running (per-split) and split-local accumulators.
    float runR[4][4] = {{0.f}}, runL[4][4] = {{0.f}}, runH[4][4] = {{0.f}};
    float accR[4][4] = {{0.f}}, accL[4][4] = {{0.f}}, accH[4][4] = {{0.f}};

    const float* __restrict__ Al = g_low;
    const float* __restrict__ Ah = g_high;

    const long long arow = (long long)(row0 + lrow) * ND;

    for (int k0 = 0; k0 < ND; k0 += BK) {
        float4 vr = *(const float4*)(Ar + arow + k0 + lk);
        float4 vl = *(const float4*)(Al + arow + k0 + lk);
        float4 vh = *(const float4*)(Ah + arow + k0 + lk);
        float4 vw = *(const float4*)(W + (long long)(k0 + brow) * ND + col0 + bcol);

        As[0][lk + 0][lrow] = vr.x;
        As[0][lk + 1][lrow] = vr.y;
        As[0][lk + 2][lrow] = vr.z;
        As[0][lk + 3][lrow] = vr.w;
        As[1][lk + 0][lrow] = vl.x;
        As[1][lk + 1][lrow] = vl.y;
        As[1][lk + 2][lrow] = vl.z;
        As[1][lk + 3][lrow] = vl.w;
        As[2][lk + 0][lrow] = vh.x;
        As[2][lk + 1][lrow] = vh.y;
        As[2][lk + 2][lrow] = vh.z;
        As[2][lk + 3][lrow] = vh.w;
        *(float4*)&Bs[brow][bcol] = vw;

        __syncthreads();

#pragma unroll
        for (int k = 0; k < BK; ++k) {
            float4 b4 = *(const float4*)&Bs[k][tx << 2];
            float4 r4 = *(const float4*)&As[0][k][ty << 2];
            float4 l4 = *(const float4*)&As[1][k][ty << 2];
            float4 h4 = *(const float4*)&As[2][k][ty << 2];
            float bb[4] = {b4.x, b4.y, b4.z, b4.w};
            float ra[4] = {r4.x, r4.y, r4.z, r4.w};
            float la[4] = {l4.x, l4.y, l4.z, l4.w};
            float ha[4] = {h4.x, h4.y, h4.z, h4.w};
#pragma unroll
            for (int m = 0; m < 4; ++m) {
#pragma unroll
                for (int n = 0; n < 4; ++n) {
                    accR[m][n] = fmaf(ra[m], bb[n], accR[m][n]);
                    accL[m][n] = fmaf(la[m], bb[n], accL[m][n]);
                    accH[m][n] = fmaf(ha[m], bb[n], accH[m][n]);
                }
            }
        }
        __syncthreads();

        // splitK fold at the 2048 boundary and at K end.
        int knext = k0 + BK;
        if ((knext % KSPLIT) == 0) {
#pragma unroll
            for (int m = 0; m < 4; ++m) {
#pragma unroll
                for (int n = 0; n < 4; ++n) {
                    runR[m][n] = __fadd_rn(runR[m][n], accR[m][n]);
                    runL[m][n] = __fadd_rn(runL[m][n], accL[m][n]);
                    runH[m][n] = __fadd_rn(runH[m][n], accH[m][n]);
                    accR[m][n] = 0.f;
                    accL[m][n] = 0.f;
                    accH[m][n] = 0.f;
                }
            }
        }
    }

    // Epilogue: exact reference combine.
#pragma unroll
    for (int m = 0; m < 4; ++m) {
        const int i = row0 + (ty << 2) + m;
#pragma unroll
        for (int n = 0; n < 4; ++n) {
            const int j = col0 + (tx << 2) + n;
            float oL = __fadd_rn(runL[m][n], bvec[j]);
            double v = __dadd_rn((double)oL,
                                 __dmul_rn(2291.0, (double)runH[m][n]));
            float f = (float)v;
            out[(long long)i * ND + j] =
                __fmul_rn(__fsub_rn(f, runR[m][n]), 0.00390625f);
        }
    }
}

extern "C" void kernel_launch(void* const* d_in, const int* in_sizes, int n_in,
                              void* d_out, int out_size) {
    const float* x = (const float*)d_in[0];
    const float* r = (const float*)d_in[1];
    const float* W = (const float*)d_in[2];
    const float* b = (const float*)d_in[3];
    float* out = (float*)d_out;

    const long long total = (long long)ND * ND;
    prep_kernel<<<(unsigned)(total / 256), 256>>>(x, r);

    dim3 grid(ND / BN, ND / BM);
    gemm3_split2_kernel<<<grid, 256>>>(r, W, b, out);
}

// round 11
// speedup vs baseline: 2.2861x; 2.2861x over previous
#include <cuda_runtime.h>
#include <cstdint>
#include <math.h>

#define ND 4096
#define BM 64
#define BN 128
#define BK 16
#define KSPLIT 2048   // cublas splitK=2: two ascending sub-chains + one f32 add

// Scratch (allocation-free): low/high digit planes.
static __device__ float g_low[(long long)ND * ND];
static __device__ float g_high[(long long)ND * ND];

// f32x2 packed helpers (per-lane IEEE RN — bit-identical to scalar FFMA/FADD)
#define FMA2(acc, a, b) asm("fma.rn.f32x2 %0, %1, %2, %0;" : "+l"(acc) : "l"(a), "l"(b))
#define ADD2(acc, v)    asm("add.rn.f32x2 %0, %0, %1;" : "+l"(acc) : "l"(v))
#define DUP2(d, s)      asm("mov.b64 %0, {%1, %1};" : "=l"(d) : "f"(s))
#define UNPK(lo, hi, v) asm("mov.b64 {%0, %1}, %2;" : "=f"(lo), "=f"(hi) : "l"(v))

// Elementwise digit split, exact jnp semantics (verified bit-exact in R10).
__global__ void __launch_bounds__(256) prep_kernel(const float* __restrict__ x,
                                                   const float* __restrict__ r) {
    long long i = (long long)blockIdx.x * 256 + threadIdx.x;
    float xv = x[i];
    float rv = r[i];
    float xb = __fadd_rn(xv, rv);
    float low = fmodf(xb, 2291.0f);
    if (low < 0.0f) low = __fadd_rn(low, 2291.0f);
    float high = rintf(__fdiv_rn(__fsub_rn(xb, low), 2291.0f));
    g_low[i] = low;
    g_high[i] = high;
}

// Fused triple-SGEMM, splitK=2 rounding (bit-exact match to reference),
// f32x2 packed math. CTA 64x128, 256 threads, 4m x 8n per thread with
// accumulator pairs along m.
__global__ void __launch_bounds__(256) gemm3_fx2_kernel(
        const float* __restrict__ Ar,
        const float* __restrict__ W,
        const float* __restrict__ bvec,
        float* __restrict__ out) {
    __shared__ __align__(16) float As[3][BK][68];   // [mat][k][m], pitch 68
    __shared__ __align__(16) float Bs[BK][132];     // [k][n],    pitch 132

    const int tid  = threadIdx.x;
    const int tx   = tid & 15;        // n group: cols 4tx & 64+4tx
    const int ty   = tid >> 4;        // m group: rows 4ty..4ty+3
    const int row0 = blockIdx.y * BM;
    const int col0 = blockIdx.x * BN;

    const int lrow = tid >> 2;          // 0..63  (A loader)
    const int lk   = (tid & 3) << 2;    // 0,4,8,12
    const int brow = tid >> 4;          // 0..15  (B loader)
    const int bcol = (tid & 15) << 2;   // 0..60

    // acc[mat][mpair][nidx]: f32x2 lanes = (m=2mp, m=2mp+1); nidx 0..3 -> 4tx+q,
    // nidx 4..7 -> 64+4tx+q.  run = splitK running sums.
    uint64_t acc[3][2][8], run[3][2][8];
#pragma unroll
    for (int m = 0; m < 3; ++m)
#pragma unroll
        for (int p = 0; p < 2; ++p)
#pragma unroll
            for (int n = 0; n < 8; ++n) { acc[m][p][n] = 0ull; run[m][p][n] = 0ull; }

    const float* __restrict__ Al = g_low;
    const float* __restrict__ Ah = g_high;
    const long long arow = (long long)(row0 + lrow) * ND;

    for (int k0 = 0; k0 < ND; k0 += BK) {
        float4 vr = *(const float4*)(Ar + arow + k0 + lk);
        float4 vl = *(const float4*)(Al + arow + k0 + lk);
        float4 vh = *(const float4*)(Ah + arow + k0 + lk);
        const float* wrow = W + (long long)(k0 + brow) * ND + col0;
        float4 w0 = *(const float4*)(wrow + bcol);
        float4 w1 = *(const float4*)(wrow + bcol + 64);

        As[0][lk + 0][lrow] = vr.x; As[0][lk + 1][lrow] = vr.y;
        As[0][lk + 2][lrow] = vr.z; As[0][lk + 3][lrow] = vr.w;
        As[1][lk + 0][lrow] = vl.x; As[1][lk + 1][lrow] = vl.y;
        As[1][lk + 2][lrow] = vl.z; As[1][lk + 3][lrow] = vl.w;
        As[2][lk + 0][lrow] = vh.x; As[2][lk + 1][lrow] = vh.y;
        As[2][lk + 2][lrow] = vh.z; As[2][lk + 3][lrow] = vh.w;
        *(float4*)&Bs[brow][bcol] = w0;
        *(float4*)&Bs[brow][bcol + 64] = w1;

        __syncthreads();

#pragma unroll
        for (int k = 0; k < BK; ++k) {
            // A pairs: 16B load -> two m-pairs per matrix (broadcast, conflict-free)
            ulonglong2 aR = *(const ulonglong2*)&As[0][k][ty << 2];
            ulonglong2 aL = *(const ulonglong2*)&As[1][k][ty << 2];
            ulonglong2 aH = *(const ulonglong2*)&As[2][k][ty << 2];
            float4 b0 = *(const float4*)&Bs[k][tx << 2];
            float4 b1 = *(const float4*)&Bs[k][64 + (tx << 2)];
            uint64_t bd[8];
            DUP2(bd[0], b0.x); DUP2(bd[1], b0.y); DUP2(bd[2], b0.z); DUP2(bd[3], b0.w);
            DUP2(bd[4], b1.x); DUP2(bd[5], b1.y); DUP2(bd[6], b1.z); DUP2(bd[7], b1.w);
#pragma unroll
            for (int n = 0; n < 8; ++n) {
                FMA2(acc[0][0][n], aR.x, bd[n]);
                FMA2(acc[0][1][n], aR.y, bd[n]);
                FMA2(acc[1][0][n], aL.x, bd[n]);
                FMA2(acc[1][1][n], aL.y, bd[n]);
                FMA2(acc[2][0][n], aH.x, bd[n]);
                FMA2(acc[2][1][n], aH.y, bd[n]);
            }
        }
        __syncthreads();

        // splitK fold at k=2048 and k=4096 (per-lane RN add, matches reference)
        int knext = k0 + BK;
        if ((knext % KSPLIT) == 0) {
#pragma unroll
            for (int m = 0; m < 3; ++m)
#pragma unroll
                for (int p = 0; p < 2; ++p)
#pragma unroll
                    for (int n = 0; n < 8; ++n) {
                        ADD2(run[m][p][n], acc[m][p][n]);
                        acc[m][p][n] = 0ull;
                    }
        }
    }

    // Epilogue: exact reference combine, vectorized float4 stores.
    float4 bv0 = *(const float4*)(bvec + col0 + (tx << 2));
    float4 bv1 = *(const float4*)(bvec + col0 + 64 + (tx << 2));
    float bj[8] = {bv0.x, bv0.y, bv0.z, bv0.w, bv1.x, bv1.y, bv1.z, bv1.w};

#pragma unroll
    for (int half = 0; half < 2; ++half) {
#pragma unroll
        for (int mm = 0; mm < 4; ++mm) {
            const int i = row0 + (ty << 2) + mm;
            const int mp = mm >> 1, lane = mm & 1;
            float o[4];
#pragma unroll
            for (int q = 0; q < 4; ++q) {
                const int n = half * 4 + q;
                float r0, r1, l0, l1, h0, h1;
                UNPK(r0, r1, run[0][mp][n]);
                UNPK(l0, l1, run[1][mp][n]);
                UNPK(h0, h1, run[2][mp][n]);
                float gR = lane ? r1 : r0;
                float gL = lane ? l1 : l0;
                float gH = lane ? h1 : h0;
                float oL = __fadd_rn(gL, bj[n]);
                double v = __dadd_rn((double)oL, __dmul_rn(2291.0, (double)gH));
                float f = (float)v;
                o[q] = __fmul_rn(__fsub_rn(f, gR), 0.00390625f);
            }
            *(float4*)(out + (long long)i * ND + col0 + half * 64 + (tx << 2)) =
                make_float4(o[0], o[1], o[2], o[3]);
        }
    }
}

extern "C" void kernel_launch(void* const* d_in, const int* in_sizes, int n_in,
                              void* d_out, int out_size) {
    const float* x = (const float*)d_in[0];
    const float* r = (const float*)d_in[1];
    const float* W = (const float*)d_in[2];
    const float* b = (const float*)d_in[3];
    float* out = (float*)d_out;

    const long long total = (long long)ND * ND;
    prep_kernel<<<(unsigned)(total / 256), 256>>>(x, r);

    dim3 grid(ND / BN, ND / BM);
    gemm3_fx2_kernel<<<grid, 256>>>(r, W, b, out);
}

// round 12
// speedup vs baseline: 2.7821x; 1.2170x over previous
#include <cuda_runtime.h>
#include <cstdint>
#include <math.h>

#define ND 4096
#define BM 64
#define BN 128
#define BK 16
#define NT (ND / BK)          // 256 k-tiles
// splitK=2 fold after tiles 127 and 255: ((t+1) & 127) == 0

// Transposed A planes [k][m] (allocation-free scratch, 64 MB each).
static __device__ float g_rT[(size_t)ND * ND];
static __device__ float g_lowT[(size_t)ND * ND];
static __device__ float g_highT[(size_t)ND * ND];

// f32x2 packed helpers (per-lane IEEE RN — bit-identical to scalar FFMA/FADD)
#define FMA2(acc, a, b) asm("fma.rn.f32x2 %0, %1, %2, %0;" : "+l"(acc) : "l"(a), "l"(b))
#define ADD2(acc, v)    asm("add.rn.f32x2 %0, %0, %1;" : "+l"(acc) : "l"(v))
#define DUP2(d, s)      asm("mov.b64 %0, {%1, %1};" : "=l"(d) : "f"(s))
#define UNPK(lo, hi, v) asm("mov.b64 {%0, %1}, %2;" : "=f"(lo), "=f"(hi) : "l"(v))

#define CP16(dst, src) \
    asm volatile("cp.async.cg.shared.global [%0], [%1], 16;" :: "r"(dst), "l"(src))

__device__ __forceinline__ uint32_t smem_u32(const void* p) {
    uint32_t a;
    asm("{ .reg .u64 t; cvta.to.shared.u64 t, %1; cvt.u32.u64 %0, t; }" : "=r"(a) : "l"(p));
    return a;
}

// Digit split (exact jnp semantics, verified bit-exact R10/R11) + 32x32
// transpose so the GEMM can cp.async A tiles directly.
__global__ void __launch_bounds__(256) prep_T(const float* __restrict__ x,
                                              const float* __restrict__ r) {
    __shared__ float tR[32][33], tL[32][33], tH[32][33];
    const int tx = threadIdx.x & 31, ty = threadIdx.x >> 5;   // 32 x 8
    const int m0 = blockIdx.x * 32, k0 = blockIdx.y * 32;
#pragma unroll
    for (int i = 0; i < 4; ++i) {
        const int ml = ty + 8 * i;
        const size_t idx = (size_t)(m0 + ml) * ND + k0 + tx;
        float rv = r[idx];
        float xb = __fadd_rn(x[idx], rv);
        float low = fmodf(xb, 2291.0f);
        if (low < 0.0f) low = __fadd_rn(low, 2291.0f);
        float high = rintf(__fdiv_rn(__fsub_rn(xb, low), 2291.0f));
        tR[ml][tx] = rv;
        tL[ml][tx] = low;
        tH[ml][tx] = high;
    }
    __syncthreads();
#pragma unroll
    for (int i = 0; i < 4; ++i) {
        const int kl = ty + 8 * i;
        const size_t o = (size_t)(k0 + kl) * ND + m0 + tx;
        g_rT[o]    = tR[tx][kl];
        g_lowT[o]  = tL[tx][kl];
        g_highT[o] = tH[tx][kl];
    }
}

// Fused triple-SGEMM, splitK=2 rounding (bit-exact), f32x2 math,
// cp.async double-buffered pipeline. CTA 64x128, 256 threads, 4m x 8n/thread.
__global__ void __launch_bounds__(256) gemm3_pipe_kernel(
        const float* __restrict__ W,
        const float* __restrict__ bvec,
        float* __restrict__ out) {
    __shared__ __align__(16) float As[2][3][BK][68];   // [buf][mat][k][m]
    __shared__ __align__(16) float Bs[2][BK][132];     // [buf][k][n]

    const int tid  = threadIdx.x;
    const int tx   = tid & 15;
    const int ty   = tid >> 4;
    const int row0 = blockIdx.y * BM;
    const int col0 = blockIdx.x * BN;

    const uint32_t sA = smem_u32(&As[0][0][0][0]);
    const uint32_t sB = smem_u32(&Bs[0][0][0]);

    // loader mapping (256 threads): A chunk -> mat=it, kr=tid>>4, qa=tid&15
    //                               B chunk -> kr=it*8+(tid>>5), qb=tid&31
    const int akr = tid >> 4, aq = tid & 15;
    const int bkr = tid >> 5, bq = tid & 31;
    const float* srcA[3] = {g_rT, g_lowT, g_highT};

    uint64_t acc[3][2][8], run[3][2][8];
#pragma unroll
    for (int m = 0; m < 3; ++m)
#pragma unroll
        for (int p = 0; p < 2; ++p)
#pragma unroll
            for (int n = 0; n < 8; ++n) { acc[m][p][n] = 0ull; run[m][p][n] = 0ull; }

#define LOAD_TILE(t, buf)                                                        \
    do {                                                                         \
        const int _k0 = (t) * BK;                                                \
        _Pragma("unroll")                                                        \
        for (int _it = 0; _it < 3; ++_it) {                                      \
            const float* _s = srcA[_it] + (size_t)(_k0 + akr) * ND + row0 + aq * 4; \
            uint32_t _d = sA + (uint32_t)((((buf) * 3 + _it) * BK + akr) * 272 + aq * 16); \
            CP16(_d, _s);                                                        \
        }                                                                        \
        _Pragma("unroll")                                                        \
        for (int _it = 0; _it < 2; ++_it) {                                      \
            const int _kr = _it * 8 + bkr;                                       \
            const float* _s = W + (size_t)(_k0 + _kr) * ND + col0 + bq * 4;      \
            uint32_t _d = sB + (uint32_t)(((buf) * BK + _kr) * 528 + bq * 16);   \
            CP16(_d, _s);                                                        \
        }                                                                        \
        asm volatile("cp.async.commit_group;" ::: "memory");                     \
    } while (0)

    LOAD_TILE(0, 0);

    for (int t = 0; t < NT; ++t) {
        const int buf = t & 1;
        if (t + 1 < NT) {
            LOAD_TILE(t + 1, (t + 1) & 1);
            asm volatile("cp.async.wait_group 1;" ::: "memory");
        } else {
            asm volatile("cp.async.wait_group 0;" ::: "memory");
        }
        __syncthreads();

#pragma unroll
        for (int k = 0; k < BK; ++k) {
            ulonglong2 aR = *(const ulonglong2*)&As[buf][0][k][ty << 2];
            ulonglong2 aL = *(const ulonglong2*)&As[buf][1][k][ty << 2];
            ulonglong2 aH = *(const ulonglong2*)&As[buf][2][k][ty << 2];
            float4 b0 = *(const float4*)&Bs[buf][k][tx << 2];
            float4 b1 = *(const float4*)&Bs[buf][k][64 + (tx << 2)];
            uint64_t bd[8];
            DUP2(bd[0], b0.x); DUP2(bd[1], b0.y); DUP2(bd[2], b0.z); DUP2(bd[3], b0.w);
            DUP2(bd[4], b1.x); DUP2(bd[5], b1.y); DUP2(bd[6], b1.z); DUP2(bd[7], b1.w);
#pragma unroll
            for (int n = 0; n < 8; ++n) {
                FMA2(acc[0][0][n], aR.x, bd[n]);
                FMA2(acc[0][1][n], aR.y, bd[n]);
                FMA2(acc[1][0][n], aL.x, bd[n]);
                FMA2(acc[1][1][n], aL.y, bd[n]);
                FMA2(acc[2][0][n], aH.x, bd[n]);
                FMA2(acc[2][1][n], aH.y, bd[n]);
            }
        }

        // splitK=2 fold after tiles 127 and 255 (register-local)
        if (((t + 1) & 127) == 0) {
#pragma unroll
            for (int m = 0; m < 3; ++m)
#pragma unroll
                for (int p = 0; p < 2; ++p)
#pragma unroll
                    for (int n = 0; n < 8; ++n) {
                        ADD2(run[m][p][n], acc[m][p][n]);
                        acc[m][p][n] = 0ull;
                    }
        }
        __syncthreads();
    }

    // Epilogue: exact reference combine, vectorized stores.
    float4 bv0 = *(const float4*)(bvec + col0 + (tx << 2));
    float4 bv1 = *(const float4*)(bvec + col0 + 64 + (tx << 2));
    float bj[8] = {bv0.x, bv0.y, bv0.z, bv0.w, bv1.x, bv1.y, bv1.z, bv1.w};

#pragma unroll
    for (int half = 0; half < 2; ++half) {
#pragma unroll
        for (int mm = 0; mm < 4; ++mm) {
            const int i = row0 + (ty << 2) + mm;
            const int mp = mm >> 1, lane = mm & 1;
            float o[4];
#pragma unroll
            for (int q = 0; q < 4; ++q) {
                const int n = half * 4 + q;
                float r0, r1, l0, l1, h0, h1;
                UNPK(r0, r1, run[0][mp][n]);
                UNPK(l0, l1, run[1][mp][n]);
                UNPK(h0, h1, run[2][mp][n]);
                float gR = lane ? r1 : r0;
                float gL = lane ? l1 : l0;
                float gH = lane ? h1 : h0;
                float oL = __fadd_rn(gL, bj[n]);
                double v = __dadd_rn((double)oL, __dmul_rn(2291.0, (double)gH));
                float f = (float)v;
                o[q] = __fmul_rn(__fsub_rn(f, gR), 0.00390625f);
            }
            *(float4*)(out + (long long)i * ND + col0 + half * 64 + (tx << 2)) =
                make_float4(o[0], o[1], o[2], o[3]);
        }
    }
}

extern "C" void kernel_launch(void* const* d_in, const int* in_sizes, int n_in,
                              void* d_out, int out_size) {
    const float* x = (const float*)d_in[0];
    const float* r = (const float*)d_in[1];
    const float* W = (const float*)d_in[2];
    const float* b = (const float*)d_in[3];
    float* out = (float*)d_out;

    dim3 gp(ND / 32, ND / 32);
    prep_T<<<gp, 256>>>(x, r);

    dim3 grid(ND / BN, ND / BM);
    gemm3_pipe_kernel<<<grid, 256>>>(W, b, out);
}

// round 14
// speedup vs baseline: 2.8770x; 1.0341x over previous
#include <cuda_runtime.h>
#include <cstdint>
#include <math.h>

#define ND 4096
#define BM 64
#define BN 128
#define BK 32
#define NT (ND / BK)          // 128 k-tiles
// splitK=2 fold after tiles 63 and 127: ((t+1) & 63) == 0

#define STG_FLOATS 10752      // per stage: A 3*32*68 + B 32*132
#define A_PITCH 68
#define B_PITCH 132
#define B_OFF_F 6528          // A floats per stage
#define SMEM_BYTES (3 * STG_FLOATS * 4)   // 129024

// Transposed A planes [k][m] (allocation-free scratch, 64 MB each).
static __device__ float g_rT[(size_t)ND * ND];
static __device__ float g_lowT[(size_t)ND * ND];
static __device__ float g_highT[(size_t)ND * ND];

// f32x2 packed helpers (per-lane IEEE RN — bit-identical to scalar FFMA/FADD)
#define FMA2(acc, a, b) asm("fma.rn.f32x2 %0, %1, %2, %0;" : "+l"(acc) : "l"(a), "l"(b))
#define ADD2(acc, v)    asm("add.rn.f32x2 %0, %0, %1;" : "+l"(acc) : "l"(v))
#define DUP2(d, s)      asm("mov.b64 %0, {%1, %1};" : "=l"(d) : "f"(s))
#define UNPK(lo, hi, v) asm("mov.b64 {%0, %1}, %2;" : "=f"(lo), "=f"(hi) : "l"(v))

#define CP16(dst, src) \
    asm volatile("cp.async.cg.shared.global [%0], [%1], 16;" :: "r"(dst), "l"(src))

__device__ __forceinline__ uint32_t smem_u32(const void* p) {
    uint32_t a;
    asm("{ .reg .u64 t; cvta.to.shared.u64 t, %1; cvt.u32.u64 %0, t; }" : "=r"(a) : "l"(p));
    return a;
}

// Digit split (exact jnp semantics, bit-exact since R10) + 32x32 transpose.
__global__ void __launch_bounds__(256) prep_T(const float* __restrict__ x,
                                              const float* __restrict__ r) {
    __shared__ float tR[32][33], tL[32][33], tH[32][33];
    const int tx = threadIdx.x & 31, ty = threadIdx.x >> 5;
    const int m0 = blockIdx.x * 32, k0 = blockIdx.y * 32;
#pragma unroll
    for (int i = 0; i < 4; ++i) {
        const int ml = ty + 8 * i;
        const size_t idx = (size_t)(m0 + ml) * ND + k0 + tx;
        float rv = r[idx];
        float xb = __fadd_rn(x[idx], rv);
        float low = fmodf(xb, 2291.0f);
        if (low < 0.0f) low = __fadd_rn(low, 2291.0f);
        float high = rintf(__fdiv_rn(__fsub_rn(xb, low), 2291.0f));
        tR[ml][tx] = rv;
        tL[ml][tx] = low;
        tH[ml][tx] = high;
    }
    __syncthreads();
#pragma unroll
    for (int i = 0; i < 4; ++i) {
        const int kl = ty + 8 * i;
        const size_t o = (size_t)(k0 + kl) * ND + m0 + tx;
        g_rT[o]    = tR[tx][kl];
        g_lowT[o]  = tL[tx][kl];
        g_highT[o] = tH[tx][kl];
    }
}

// Fused triple-SGEMM, splitK=2 rounding (bit-exact), f32x2 math,
// 3-stage cp.async pipeline. ONE barrier per tile, prefetch issued AFTER
// the barrier so buffer (t+2)%3 is only written once all warps finished
// computing tile t-1 from it (race fixed vs R13).
__global__ void __launch_bounds__(256) gemm3_pipe3_kernel(
        const float* __restrict__ W,
        const float* __restrict__ bvec,
        float* __restrict__ out) {
    extern __shared__ __align__(16) float smem[];

    const int tid  = threadIdx.x;
    const int tx   = tid & 15;
    const int ty   = tid >> 4;
    const int row0 = blockIdx.y * BM;
    const int col0 = blockIdx.x * BN;

    const uint32_t sbase = smem_u32(smem);
    const float* srcA[3] = {g_rT, g_lowT, g_highT};

    uint64_t acc[3][2][8], run[3][2][8];
#pragma unroll
    for (int m = 0; m < 3; ++m)
#pragma unroll
        for (int p = 0; p < 2; ++p)
#pragma unroll
            for (int n = 0; n < 8; ++n) { acc[m][p][n] = 0ull; run[m][p][n] = 0ull; }

    // Loader: A = 1536 float4 (6/thread), B = 1024 float4 (4/thread)
#define LOAD_TILE(t, stg)                                                         \
    do {                                                                          \
        const int _k0 = (t) * BK;                                                 \
        const uint32_t _sb = sbase + (uint32_t)(stg) * (STG_FLOATS * 4);          \
        _Pragma("unroll")                                                         \
        for (int _i = 0; _i < 6; ++_i) {                                          \
            const int _lin = _i * 256 + tid;                                      \
            const int _pl = _lin >> 9, _kr = (_lin >> 4) & 31, _q = _lin & 15;    \
            const float* _s = srcA[_pl] + (size_t)(_k0 + _kr) * ND + row0 + _q * 4; \
            CP16(_sb + (uint32_t)((_pl * 32 + _kr) * (A_PITCH * 4) + _q * 16), _s); \
        }                                                                         \
        _Pragma("unroll")                                                         \
        for (int _i = 0; _i < 4; ++_i) {                                          \
            const int _lin = _i * 256 + tid;                                      \
            const int _kr = _lin >> 5, _q = _lin & 31;                            \
            const float* _s = W + (size_t)(_k0 + _kr) * ND + col0 + _q * 4;       \
            CP16(_sb + (uint32_t)(B_OFF_F * 4 + _kr * (B_PITCH * 4) + _q * 16), _s); \
        }                                                                         \
    } while (0)

    LOAD_TILE(0, 0);
    asm volatile("cp.async.commit_group;" ::: "memory");
    LOAD_TILE(1, 1);
    asm volatile("cp.async.commit_group;" ::: "memory");

    int stage = 0;
    for (int t = 0; t < NT; ++t) {
        // tile t = second-newest committed group -> wait_group 1
        asm volatile("cp.async.wait_group 1;" ::: "memory");
        __syncthreads();
        // Prefetch AFTER the barrier: all warps have finished compute(t-1)
        // on buffer (t+2)%3, so overwriting it now is safe.
        if (t + 2 < NT) LOAD_TILE(t + 2, (stage + 2) % 3);
        asm volatile("cp.async.commit_group;" ::: "memory");   // one group/iter

        const float* As = smem + stage * STG_FLOATS;
        const float* Bs = As + B_OFF_F;

#pragma unroll
        for (int k = 0; k < BK; ++k) {
            ulonglong2 aR = *(const ulonglong2*)(As + (0 * 32 + k) * A_PITCH + (ty << 2));
            ulonglong2 aL = *(const ulonglong2*)(As + (1 * 32 + k) * A_PITCH + (ty << 2));
            ulonglong2 aH = *(const ulonglong2*)(As + (2 * 32 + k) * A_PITCH + (ty << 2));
            float4 b0 = *(const float4*)(Bs + k * B_PITCH + (tx << 2));
            float4 b1 = *(const float4*)(Bs + k * B_PITCH + 64 + (tx << 2));
            uint64_t bd[8];
            DUP2(bd[0], b0.x); DUP2(bd[1], b0.y); DUP2(bd[2], b0.z); DUP2(bd[3], b0.w);
            DUP2(bd[4], b1.x); DUP2(bd[5], b1.y); DUP2(bd[6], b1.z); DUP2(bd[7], b1.w);
#pragma unroll
            for (int n = 0; n < 8; ++n) {
                FMA2(acc[0][0][n], aR.x, bd[n]);
                FMA2(acc[0][1][n], aR.y, bd[n]);
                FMA2(acc[1][0][n], aL.x, bd[n]);
                FMA2(acc[1][1][n], aL.y, bd[n]);
                FMA2(acc[2][0][n], aH.x, bd[n]);
                FMA2(acc[2][1][n], aH.y, bd[n]);
            }
        }

        // splitK=2 fold after tiles 63 and 127 (k=2048, 4096)
        if (((t + 1) & 63) == 0) {
#pragma unroll
            for (int m = 0; m < 3; ++m)
#pragma unroll
                for (int p = 0; p < 2; ++p)
#pragma unroll
                    for (int n = 0; n < 8; ++n) {
                        ADD2(run[m][p][n], acc[m][p][n]);
                        acc[m][p][n] = 0ull;
                    }
        }
        stage = (stage + 1) % 3;
    }

    // Epilogue: exact reference combine, vectorized stores.
    float4 bv0 = *(const float4*)(bvec + col0 + (tx << 2));
    float4 bv1 = *(const float4*)(bvec + col0 + 64 + (tx << 2));
    float bj[8] = {bv0.x, bv0.y, bv0.z, bv0.w, bv1.x, bv1.y, bv1.z, bv1.w};

#pragma unroll
    for (int half = 0; half < 2; ++half) {
#pragma unroll
        for (int mm = 0; mm < 4; ++mm) {
            const int i = row0 + (ty << 2) + mm;
            const int mp = mm >> 1, lane = mm & 1;
            float o[4];
#pragma unroll
            for (int q = 0; q < 4; ++q) {
                const int n = half * 4 + q;
                float r0, r1, l0, l1, h0, h1;
                UNPK(r0, r1, run[0][mp][n]);
                UNPK(l0, l1, run[1][mp][n]);
                UNPK(h0, h1, run[2][mp][n]);
                float gR = lane ? r1 : r0;
                float gL = lane ? l1 : l0;
                float gH = lane ? h1 : h0;
                float oL = __fadd_rn(gL, bj[n]);
                double v = __dadd_rn((double)oL, __dmul_rn(2291.0, (double)gH));
                float f = (float)v;
                o[q] = __fmul_rn(__fsub_rn(f, gR), 0.00390625f);
            }
            *(float4*)(out + (long long)i * ND + col0 + half * 64 + (tx << 2)) =
                make_float4(o[0], o[1], o[2], o[3]);
        }
    }
}

extern "C" void kernel_launch(void* const* d_in, const int* in_sizes, int n_in,
                              void* d_out, int out_size) {
    const float* x = (const float*)d_in[0];
    const float* r = (const float*)d_in[1];
    const float* W = (const float*)d_in[2];
    const float* b = (const float*)d_in[3];
    float* out = (float*)d_out;

    dim3 gp(ND / 32, ND / 32);
    prep_T<<<gp, 256>>>(x, r);

    cudaFuncSetAttribute(gemm3_pipe3_kernel,
                         cudaFuncAttributeMaxDynamicSharedMemorySize, SMEM_BYTES);
    dim3 grid(ND / BN, ND / BM);
    gemm3_pipe3_kernel<<<grid, 256, SMEM_BYTES>>>(W, b, out);
}